// round 1
// baseline (speedup 1.0000x reference)
#include <cuda_runtime.h>
#include <math.h>

#define NN 50000
#define NE 1600000
#define CH 128
#define FE 50

// Device-global scratch (allocation-free rule: __device__ arrays are allowed)
__device__ float g_h[(size_t)NN * CH];
__device__ float g_agg[(size_t)NN * CH];

__device__ __forceinline__ float ssp(float x) {
    // softplus(x) - log(2), numerically stable
    return fmaxf(x, 0.0f) + log1pf(__expf(-fabsf(x))) - 0.69314718055994530942f;
}

__device__ __forceinline__ void red_add_v4(float* addr, float4 v) {
    asm volatile("red.global.add.v4.f32 [%0], {%1,%2,%3,%4};"
                 :: "l"(addr), "f"(v.x), "f"(v.y), "f"(v.z), "f"(v.w)
                 : "memory");
}

#define FMA8(ar, av, w0, w1)                 \
    ar[0] = fmaf(av, w0.x, ar[0]);           \
    ar[1] = fmaf(av, w0.y, ar[1]);           \
    ar[2] = fmaf(av, w0.z, ar[2]);           \
    ar[3] = fmaf(av, w0.w, ar[3]);           \
    ar[4] = fmaf(av, w1.x, ar[4]);           \
    ar[5] = fmaf(av, w1.y, ar[5]);           \
    ar[6] = fmaf(av, w1.z, ar[6]);           \
    ar[7] = fmaf(av, w1.w, ar[7]);

// ---------------------------------------------------------------------------
// Zero the aggregation buffer
// ---------------------------------------------------------------------------
__global__ void zero_agg_kernel() {
    size_t i = (size_t)blockIdx.x * blockDim.x + threadIdx.x;
    size_t stride = (size_t)gridDim.x * blockDim.x;
    float4* p = reinterpret_cast<float4*>(g_agg);
    const size_t n4 = (size_t)NN * CH / 4;
    float4 z = make_float4(0.f, 0.f, 0.f, 0.f);
    for (; i < n4; i += stride) p[i] = z;
}

// ---------------------------------------------------------------------------
// h = features @ W_lin^T   (h[n][c] = sum_k feat[n][k] * W[c][k])
// Block: 256 threads, tile of 128 nodes, 8x8 register micro-tile per thread.
// ---------------------------------------------------------------------------
__global__ __launch_bounds__(256, 1)
void node_linear_kernel(const float* __restrict__ feat, const float* __restrict__ W)
{
    extern __shared__ float sm[];
    float* Wt = sm;                  // [128][132]  Wt[k*132+c] = W[c*128+k]
    float* fS = sm + CH * 132;       // [128][130]
    const int tid = threadIdx.x;
    const int n0 = blockIdx.x * 128;

    // Load W transposed (coalesced global reads; padded smem rows)
    for (int i = tid; i < CH * CH; i += 256) {
        int c = i >> 7, k = i & 127;
        Wt[k * 132 + c] = W[i];
    }
    // Load feature tile
    for (int i = tid; i < 128 * (CH / 4); i += 256) {
        int r = i >> 5, k4 = i & 31;
        int n = n0 + r;
        float4 v = make_float4(0.f, 0.f, 0.f, 0.f);
        if (n < NN) v = reinterpret_cast<const float4*>(feat)[(size_t)n * (CH / 4) + k4];
        float* p = fS + r * 130 + k4 * 4;
        p[0] = v.x; p[1] = v.y; p[2] = v.z; p[3] = v.w;
    }
    __syncthreads();

    const int ei = tid >> 4;         // node octet 0..15
    const int c0 = (tid & 15) * 8;   // column start

    float acc[8][8];
    #pragma unroll
    for (int r = 0; r < 8; r++)
        #pragma unroll
        for (int j = 0; j < 8; j++) acc[r][j] = 0.f;

    #pragma unroll 2
    for (int k = 0; k < CH; k++) {
        float a[8];
        #pragma unroll
        for (int r = 0; r < 8; r++) a[r] = fS[(ei * 8 + r) * 130 + k];
        float4 w0 = *reinterpret_cast<const float4*>(Wt + k * 132 + c0);
        float4 w1 = *reinterpret_cast<const float4*>(Wt + k * 132 + c0 + 4);
        #pragma unroll
        for (int r = 0; r < 8; r++) { FMA8(acc[r], a[r], w0, w1); }
    }

    #pragma unroll
    for (int r = 0; r < 8; r++) {
        int n = n0 + ei * 8 + r;
        if (n < NN) {
            float* dst = g_h + (size_t)n * CH + c0;
            *reinterpret_cast<float4*>(dst)     = make_float4(acc[r][0], acc[r][1], acc[r][2], acc[r][3]);
            *reinterpret_cast<float4*>(dst + 4) = make_float4(acc[r][4], acc[r][5], acc[r][6], acc[r][7]);
        }
    }
}

// ---------------------------------------------------------------------------
// Fused edge kernel: gaussian basis -> ssp(basis@Wf1+b)@Wf2+b -> gather h,
// multiply, vector-atomic scatter into agg.
// Block: 256 threads, 128 edges per block.
// ---------------------------------------------------------------------------
__global__ __launch_bounds__(256, 1)
void edge_kernel(const float* __restrict__ dist,
                 const float* __restrict__ Wf1, const float* __restrict__ bf1,
                 const float* __restrict__ Wf2, const float* __restrict__ bf2,
                 const int* __restrict__ senders, const int* __restrict__ receivers)
{
    extern __shared__ float sm[];
    float* Wf1s  = sm;                       // 50*128   = 6400
    float* Wf2s  = Wf1s + FE * CH;           // 128*128  = 16384
    float* bf1s  = Wf2s + CH * CH;           // 128
    float* bf2s  = bf1s + CH;                // 128
    float* basis = bf2s + CH;                // 128*53   = 6784
    float* t1    = basis + 128 * 53;         // 128*130  = 16640

    const int tid = threadIdx.x;
    const int e0 = blockIdx.x * 128;

    for (int i = tid; i < FE * CH; i += 256) Wf1s[i] = Wf1[i];
    for (int i = tid; i < CH * CH; i += 256) Wf2s[i] = Wf2[i];
    if (tid < CH) { bf1s[tid] = bf1[tid]; bf2s[tid] = bf2[tid]; }

    // Gaussian smearing: centers f*delta, coef = 1/(2 delta^2)
    const float delta = 5.0f / 49.0f;
    const float coef  = (49.0f * 49.0f) / 50.0f;   // 1/(2*delta^2) = 48.02
    for (int i = tid; i < 128 * FE; i += 256) {
        int e = i / FE, f = i - e * FE;
        float r = dist[e0 + e];
        float d = r - delta * (float)f;
        basis[e * 53 + f] = __expf(-coef * d * d);
    }
    __syncthreads();

    const int ei = tid >> 4;
    const int c0 = (tid & 15) * 8;

    // ---- stage 1: t1 = ssp(basis @ Wf1 + bf1) ----
    float acc[8][8];
    #pragma unroll
    for (int r = 0; r < 8; r++)
        #pragma unroll
        for (int j = 0; j < 8; j++) acc[r][j] = bf1s[c0 + j];

    #pragma unroll 2
    for (int f = 0; f < FE; f++) {
        float a[8];
        #pragma unroll
        for (int r = 0; r < 8; r++) a[r] = basis[(ei * 8 + r) * 53 + f];
        float4 w0 = *reinterpret_cast<const float4*>(Wf1s + f * CH + c0);
        float4 w1 = *reinterpret_cast<const float4*>(Wf1s + f * CH + c0 + 4);
        #pragma unroll
        for (int r = 0; r < 8; r++) { FMA8(acc[r], a[r], w0, w1); }
    }
    #pragma unroll
    for (int r = 0; r < 8; r++)
        #pragma unroll
        for (int j = 0; j < 8; j++)
            t1[(ei * 8 + r) * 130 + c0 + j] = ssp(acc[r][j]);
    __syncthreads();

    // ---- stage 2: ef = t1 @ Wf2 + bf2 ----
    #pragma unroll
    for (int r = 0; r < 8; r++)
        #pragma unroll
        for (int j = 0; j < 8; j++) acc[r][j] = bf2s[c0 + j];

    #pragma unroll 2
    for (int k = 0; k < CH; k++) {
        float a[8];
        #pragma unroll
        for (int r = 0; r < 8; r++) a[r] = t1[(ei * 8 + r) * 130 + k];
        float4 w0 = *reinterpret_cast<const float4*>(Wf2s + k * CH + c0);
        float4 w1 = *reinterpret_cast<const float4*>(Wf2s + k * CH + c0 + 4);
        #pragma unroll
        for (int r = 0; r < 8; r++) { FMA8(acc[r], a[r], w0, w1); }
    }

    // ---- stage 3: messages = h[senders] * ef ; scatter-add into agg ----
    #pragma unroll
    for (int r = 0; r < 8; r++) {
        int e = e0 + ei * 8 + r;
        int s   = senders[e];
        int rcv = receivers[e];
        const float* hp = g_h + (size_t)s * CH + c0;
        float4 h0 = *reinterpret_cast<const float4*>(hp);
        float4 h1 = *reinterpret_cast<const float4*>(hp + 4);
        float4 m0 = make_float4(acc[r][0] * h0.x, acc[r][1] * h0.y,
                                acc[r][2] * h0.z, acc[r][3] * h0.w);
        float4 m1 = make_float4(acc[r][4] * h1.x, acc[r][5] * h1.y,
                                acc[r][6] * h1.z, acc[r][7] * h1.w);
        float* dst = g_agg + (size_t)rcv * CH + c0;
        red_add_v4(dst, m0);
        red_add_v4(dst + 4, m1);
    }
}

// ---------------------------------------------------------------------------
// out = ssp(agg @ Wm1 + bm1) @ Wm2 + bm2
// Block: 256 threads, tile of 128 nodes; weight buffer reused across stages.
// ---------------------------------------------------------------------------
__global__ __launch_bounds__(256, 1)
void out_mlp_kernel(const float* __restrict__ Wm1, const float* __restrict__ bm1,
                    const float* __restrict__ Wm2, const float* __restrict__ bm2,
                    float* __restrict__ out)
{
    extern __shared__ float sm[];
    float* Ws  = sm;                  // 16384 (Wm1 then Wm2)
    float* bs  = Ws + CH * CH;        // 128
    float* inS = bs + CH;             // 128*130 = 16640
    float* tS  = inS + 128 * 130;     // 128*130 = 16640

    const int tid = threadIdx.x;
    const int n0 = blockIdx.x * 128;

    for (int i = tid; i < CH * CH; i += 256) Ws[i] = Wm1[i];
    if (tid < CH) bs[tid] = bm1[tid];
    for (int i = tid; i < 128 * (CH / 4); i += 256) {
        int r = i >> 5, k4 = i & 31;
        int n = n0 + r;
        float4 v = make_float4(0.f, 0.f, 0.f, 0.f);
        if (n < NN) v = reinterpret_cast<const float4*>(g_agg)[(size_t)n * (CH / 4) + k4];
        float* p = inS + r * 130 + k4 * 4;
        p[0] = v.x; p[1] = v.y; p[2] = v.z; p[3] = v.w;
    }
    __syncthreads();

    const int ei = tid >> 4;
    const int c0 = (tid & 15) * 8;

    float acc[8][8];
    #pragma unroll
    for (int r = 0; r < 8; r++)
        #pragma unroll
        for (int j = 0; j < 8; j++) acc[r][j] = bs[c0 + j];

    #pragma unroll 2
    for (int k = 0; k < CH; k++) {
        float a[8];
        #pragma unroll
        for (int r = 0; r < 8; r++) a[r] = inS[(ei * 8 + r) * 130 + k];
        float4 w0 = *reinterpret_cast<const float4*>(Ws + k * CH + c0);
        float4 w1 = *reinterpret_cast<const float4*>(Ws + k * CH + c0 + 4);
        #pragma unroll
        for (int r = 0; r < 8; r++) { FMA8(acc[r], a[r], w0, w1); }
    }
    #pragma unroll
    for (int r = 0; r < 8; r++)
        #pragma unroll
        for (int j = 0; j < 8; j++)
            tS[(ei * 8 + r) * 130 + c0 + j] = ssp(acc[r][j]);
    __syncthreads();

    // reload weights for stage 2
    for (int i = tid; i < CH * CH; i += 256) Ws[i] = Wm2[i];
    if (tid < CH) bs[tid] = bm2[tid];
    __syncthreads();

    #pragma unroll
    for (int r = 0; r < 8; r++)
        #pragma unroll
        for (int j = 0; j < 8; j++) acc[r][j] = bs[c0 + j];

    #pragma unroll 2
    for (int k = 0; k < CH; k++) {
        float a[8];
        #pragma unroll
        for (int r = 0; r < 8; r++) a[r] = tS[(ei * 8 + r) * 130 + k];
        float4 w0 = *reinterpret_cast<const float4*>(Ws + k * CH + c0);
        float4 w1 = *reinterpret_cast<const float4*>(Ws + k * CH + c0 + 4);
        #pragma unroll
        for (int r = 0; r < 8; r++) { FMA8(acc[r], a[r], w0, w1); }
    }

    #pragma unroll
    for (int r = 0; r < 8; r++) {
        int n = n0 + ei * 8 + r;
        if (n < NN) {
            float* dst = out + (size_t)n * CH + c0;
            *reinterpret_cast<float4*>(dst)     = make_float4(acc[r][0], acc[r][1], acc[r][2], acc[r][3]);
            *reinterpret_cast<float4*>(dst + 4) = make_float4(acc[r][4], acc[r][5], acc[r][6], acc[r][7]);
        }
    }
}

// ---------------------------------------------------------------------------
extern "C" void kernel_launch(void* const* d_in, const int* in_sizes, int n_in,
                              void* d_out, int out_size)
{
    const float* features = (const float*)d_in[0];
    const float* dist     = (const float*)d_in[1];
    const float* W_lin    = (const float*)d_in[2];
    const float* Wf1      = (const float*)d_in[3];
    const float* bf1      = (const float*)d_in[4];
    const float* Wf2      = (const float*)d_in[5];
    const float* bf2      = (const float*)d_in[6];
    const float* Wm1      = (const float*)d_in[7];
    const float* bm1      = (const float*)d_in[8];
    const float* Wm2      = (const float*)d_in[9];
    const float* bm2      = (const float*)d_in[10];
    const int*   senders   = (const int*)d_in[11];
    const int*   receivers = (const int*)d_in[12];
    float* out = (float*)d_out;

    const int smemA = (CH * 132 + 128 * 130) * 4;                                   // 134144
    const int smemB = (FE * CH + CH * CH + 2 * CH + 128 * 53 + 128 * 130) * 4;      // 185856
    const int smemC = (CH * CH + CH + 2 * 128 * 130) * 4;                           // 199168

    cudaFuncSetAttribute(node_linear_kernel, cudaFuncAttributeMaxDynamicSharedMemorySize, smemA);
    cudaFuncSetAttribute(edge_kernel,        cudaFuncAttributeMaxDynamicSharedMemorySize, smemB);
    cudaFuncSetAttribute(out_mlp_kernel,     cudaFuncAttributeMaxDynamicSharedMemorySize, smemC);

    zero_agg_kernel<<<1024, 256>>>();
    node_linear_kernel<<<(NN + 127) / 128, 256, smemA>>>(features, W_lin);
    edge_kernel<<<NE / 128, 256, smemB>>>(dist, Wf1, bf1, Wf2, bf2, senders, receivers);
    out_mlp_kernel<<<(NN + 127) / 128, 256, smemC>>>(Wm1, bm1, Wm2, bm2, out);
}